// round 13
// baseline (speedup 1.0000x reference)
#include <cuda_runtime.h>
#include <math_constants.h>

#define NROWS 4096
#define M_REC 4000
#define M_SUB 20000
#define MAXG  10
#define TBLK  128   // tail blocks (all simultaneously resident: 128 < 148 SMs)

// Scratch (allocation-free per harness rules)
__device__ int      g_ri[NROWS];
__device__ int      g_si[NROWS];
__device__ int2     g_tab[NROWS];   // {si, p_self} per j
__device__ unsigned g_ctr = 0;      // monotonic ticket counter (never reset)

// ---------------------------------------------------------------------------
// Row argmax: one block per row, float4 vectorized, 4-deep load batch.
// Pinned at ~6.0 TB/s (measured ceiling across 5 configs) — do not touch.
// Tie-break matches jnp.argmax (first index).
// ---------------------------------------------------------------------------
template <int M>
__device__ __forceinline__ void row_argmax(const float* __restrict__ mat,
                                           int row, int* __restrict__ out_idx)
{
    const float4* __restrict__ rp =
        reinterpret_cast<const float4*>(mat + (size_t)row * M);
    constexpr int M4 = M / 4;   // both 4000 and 20000 divisible by 4

    float best = -CUDART_INF_F;
    int   bvec = (threadIdx.x < M4) ? (int)threadIdx.x : 0;

    int i = threadIdx.x;
    for (; i + 3 * 256 < M4; i += 4 * 256) {
        float4 v0 = rp[i];
        float4 v1 = rp[i + 256];
        float4 v2 = rp[i + 512];
        float4 v3 = rp[i + 768];
        float m0 = fmaxf(fmaxf(v0.x, v0.y), fmaxf(v0.z, v0.w));
        float m1 = fmaxf(fmaxf(v1.x, v1.y), fmaxf(v1.z, v1.w));
        float m2 = fmaxf(fmaxf(v2.x, v2.y), fmaxf(v2.z, v2.w));
        float m3 = fmaxf(fmaxf(v3.x, v3.y), fmaxf(v3.z, v3.w));
        // strict '>' keeps the earliest vector on ties (ascending visit order)
        if (m0 > best) { best = m0; bvec = i;       }
        if (m1 > best) { best = m1; bvec = i + 256; }
        if (m2 > best) { best = m2; bvec = i + 512; }
        if (m3 > best) { best = m3; bvec = i + 768; }
    }
    for (; i < M4; i += 256) {
        float4 v = rp[i];
        float m = fmaxf(fmaxf(v.x, v.y), fmaxf(v.z, v.w));
        if (m > best) { best = m; bvec = i; }
    }

    // Recover lane within winning vector (first equality = smallest index).
    // best is bit-identical to one of the 4 elements, so '==' is exact.
    {
        float4 v = rp[bvec];
        int b = bvec * 4;
        int bidx = b + 3;
        if (v.z == best) bidx = b + 2;
        if (v.y == best) bidx = b + 1;
        if (v.x == best) bidx = b;
        bvec = bidx;
    }
    int bidx = bvec;

    #pragma unroll
    for (int off = 16; off > 0; off >>= 1) {
        float ov = __shfl_down_sync(0xFFFFFFFFu, best, off);
        int   oi = __shfl_down_sync(0xFFFFFFFFu, bidx, off);
        if (ov > best || (ov == best && oi < bidx)) { best = ov; bidx = oi; }
    }

    __shared__ float s_val[8];
    __shared__ int   s_idx[8];
    const int wid = threadIdx.x >> 5;
    const int lid = threadIdx.x & 31;
    if (lid == 0) { s_val[wid] = best; s_idx[wid] = bidx; }
    __syncthreads();
    if (wid == 0) {
        best = (lid < 8) ? s_val[lid] : -CUDART_INF_F;
        bidx = (lid < 8) ? s_idx[lid] : 0x7FFFFFFF;
        #pragma unroll
        for (int off = 4; off > 0; off >>= 1) {
            float ov = __shfl_down_sync(0xFFFFFFFFu, best, off);
            int   oi = __shfl_down_sync(0xFFFFFFFFu, bidx, off);
            if (ov > best || (ov == best && oi < bidx)) { best = ov; bidx = oi; }
        }
        if (lid == 0) out_idx[row] = bidx;
    }
}

__global__ void __launch_bounds__(256) argmax_both_kernel(
    const float* __restrict__ rec, const float* __restrict__ sub,
    int* __restrict__ ri, int* __restrict__ si)
{
    if (blockIdx.x < NROWS)
        row_argmax<M_SUB>(sub, blockIdx.x, si);
    else
        row_argmax<M_REC>(rec, blockIdx.x - NROWS, ri);
}

// ---------------------------------------------------------------------------
// Fused tail: prep (scattered gathers, Tprefer, Thaptic) + Tsocial in ONE
// kernel, synced by a device-wide ticket counter (all 128 blocks are
// simultaneously resident -> wait-only sync is deadlock-free).
//
// Phase A (threads 0-31 of block b, j = 32b + t): 3 dependent load rounds,
//   each round 4096-way parallel chip-wide:
//     round 1: si[j], ri[j]; round 2: preference[s*N+j], Vid[10+r];
//     round 3: preference[v*N+j], structure[s*M_REC+r].
//   Writes g_tab[j], Tprefer (out[j]), Thaptic (out[2N+j]).
// Sync: __threadfence (release) + ticket on monotonic g_ctr; target =
//   (ticket/TBLK+1)*TBLK makes the scheme correct across graph replays
//   without ever resetting the counter (deterministic results).
// Phase B: coalesced 32 KB g_tab load (L2-hot: just written), then the
//   conflict-free scan: warp's 16 sub-lanes read 16 consecutive int2
//   (128 B = 32 banks) with 2x broadcast across its 2 i-groups.
// NOTE: Vid is int32 on-device (JAX default config downcasts jnp.int64).
// ---------------------------------------------------------------------------
__global__ void __launch_bounds__(512) tail_kernel(
    const float* __restrict__ preference,
    const float* __restrict__ structure,
    const int*   __restrict__ Vid,
    float* __restrict__ out)
{
    __shared__ int2 sj[NROWS];   // 32 KB

    // ---- Phase A: this block's 32-j prep slice (threads 0-31) ----
    if (threadIdx.x < 32) {
        const int j = blockIdx.x * 32 + threadIdx.x;
        const int s = g_si[j];
        const int r = g_ri[j];
        const float p = __ldg(&preference[(size_t)s * NROWS + j]);
        const int   v = Vid[MAXG + r];        // vid_s[ri[j]], 0 <= v < P
        const float po = __ldg(&preference[(size_t)v * NROWS + j]);
        const float th = __ldg(&structure[(size_t)s * M_REC + r]);
        g_tab[j] = make_int2(s, __float_as_int(p));
        out[j] = p - po;                      // Tprefer
        out[2 * NROWS + j] = th;              // Thaptic
    }
    __syncthreads();

    // ---- Device-wide sync: all 128 prep slices complete ----
    if (threadIdx.x == 0) {
        __threadfence();                              // release g_tab writes
        const unsigned ticket = atomicAdd(&g_ctr, 1u);
        const unsigned target = (ticket / TBLK + 1u) * TBLK;
        while (atomicAdd(&g_ctr, 0u) < target) { }    // strong read, no L1
    }
    __syncthreads();
    __threadfence();                                  // acquire

    // ---- Phase B: coalesced table load + Tsocial scan ----
    #pragma unroll
    for (int k = 0; k < NROWS / 512; k++)
        sj[threadIdx.x + k * 512] = g_tab[threadIdx.x + k * 512];
    __syncthreads();

    const int i_local = threadIdx.x >> 4;       // 0..31
    const int sub     = threadIdx.x & 15;       // 0..15
    const int i       = blockIdx.x * 32 + i_local;

    const int   si_i = sj[i].x;
    const float p_i  = __int_as_float(sj[i].y);

    float acc = 0.0f;
    #pragma unroll 16
    for (int k = 0; k < NROWS / 16; k++) {
        const int2 v = sj[k * 16 + sub];
        if (v.x == si_i) acc += fminf(p_i, __int_as_float(v.y));
    }

    // Reduce the 16 sub-lanes of this i (consecutive lanes in the warp).
    #pragma unroll
    for (int off = 8; off > 0; off >>= 1)
        acc += __shfl_down_sync(0xFFFFFFFFu, acc, off);

    // Scan included j == i (si_i == si_i always); fminf(p_i, p_i) == p_i.
    if (sub == 0) out[NROWS + i] = acc - p_i;
}

// ---------------------------------------------------------------------------
extern "C" void kernel_launch(void* const* d_in, const int* in_sizes, int n_in,
                              void* d_out, int out_size)
{
    const float* Recommended_m = (const float*)d_in[0];
    const float* Substitute_m  = (const float*)d_in[1];
    // d_in[2] ItemGroups_m : unused
    const int*   Vid           = (const int*)d_in[3];
    // d_in[4..7] VUU/KUU/Vscore/Kscore : unused
    const float* preference    = (const float*)d_in[8];
    const float* structure     = (const float*)d_in[9];
    float* out = (float*)d_out;

    int* d_ri; int* d_si;
    cudaGetSymbolAddress((void**)&d_ri, g_ri);
    cudaGetSymbolAddress((void**)&d_si, g_si);

    argmax_both_kernel<<<2 * NROWS, 256>>>(Recommended_m, Substitute_m, d_ri, d_si);
    tail_kernel<<<TBLK, 512>>>(preference, structure, Vid, out);
}